// round 1
// baseline (speedup 1.0000x reference)
#include <cuda_runtime.h>
#include <cuda_bf16.h>

#define C 128
#define N_MAX 50000
#define E_MAX 625000

// ---------------- scratch (static device globals; no allocation) -------------
__device__ float g_xw[N_MAX * C];        // X @ W
__device__ float g_dinv[N_MAX];          // deg^{-1/2}
__device__ int   g_deg[N_MAX];           // out-degree by row
__device__ int   g_cnt[N_MAX];           // in-degree by col (CSR counts)
__device__ int   g_off[N_MAX + 1];       // CSR offsets (exclusive scan of g_cnt)
__device__ int   g_cur[N_MAX];           // scatter cursors
__device__ int   g_srow[E_MAX];          // sorted-by-col: source node
__device__ float g_snorm[E_MAX];         // sorted-by-col: norm coefficient
__device__ int   g_skey[E_MAX];          // sorted-by-col: packed bond-feature key
__device__ float g_combo[60 * C];        // emb0[f0]+emb1[f1]+emb2[f2] for all combos

// ---------------- kernels ----------------------------------------------------

__global__ void k_zero(int n) {
    int i = blockIdx.x * blockDim.x + threadIdx.x;
    if (i < n) { g_deg[i] = 0; g_cnt[i] = 0; }
}

__global__ void k_count(const int* __restrict__ row, const int* __restrict__ col, int e) {
    int i = blockIdx.x * blockDim.x + threadIdx.x;
    if (i < e) {
        atomicAdd(&g_deg[row[i]], 1);
        atomicAdd(&g_cnt[col[i]], 1);
    }
}

__global__ void k_dinv(int n) {
    int i = blockIdx.x * blockDim.x + threadIdx.x;
    if (i < n) {
        int d = g_deg[i];
        g_dinv[i] = (d > 0) ? rsqrtf((float)d) : 0.0f;
    }
}

// combined bond-embedding table: 60 combos x 128 channels
__global__ void k_combo(const float* __restrict__ e0, const float* __restrict__ e1,
                        const float* __restrict__ e2) {
    int c = blockIdx.x;      // 0..59
    int k = threadIdx.x;     // 0..127
    int f0 = c % 5, f1 = (c / 5) % 6, f2 = c / 30;
    g_combo[c * C + k] = e0[f0 * C + k] + e1[f1 * C + k] + e2[f2 * C + k];
}

// single-block exclusive scan of g_cnt -> g_off (+ copy to g_cur), carry-chained
__global__ void k_scan(int n) {
    __shared__ int wsum[32];
    __shared__ int carry_s;
    int tid = threadIdx.x, lane = tid & 31, wid = tid >> 5;
    if (tid == 0) carry_s = 0;
    __syncthreads();
    for (int base = 0; base < n; base += 1024) {
        int i = base + tid;
        int v = (i < n) ? g_cnt[i] : 0;
        int x = v;
        #pragma unroll
        for (int o = 1; o < 32; o <<= 1) {
            int t = __shfl_up_sync(0xFFFFFFFFu, x, o);
            if (lane >= o) x += t;
        }
        if (lane == 31) wsum[wid] = x;
        __syncthreads();
        if (wid == 0) {
            int s = wsum[lane];
            #pragma unroll
            for (int o = 1; o < 32; o <<= 1) {
                int t = __shfl_up_sync(0xFFFFFFFFu, s, o);
                if (lane >= o) s += t;
            }
            wsum[lane] = s;
        }
        __syncthreads();
        int incl = x + (wid > 0 ? wsum[wid - 1] : 0);
        int carry = carry_s;
        if (i < n) {
            int ex = carry + incl - v;
            g_off[i] = ex;
            g_cur[i] = ex;
        }
        __syncthreads();
        if (tid == 1023) carry_s = carry + wsum[31];
        __syncthreads();
    }
    if (threadIdx.x == 0) g_off[n] = carry_s;
}

// bucket edges by destination; precompute per-edge norm and packed feature key
__global__ void k_scatter(const int* __restrict__ row, const int* __restrict__ col,
                          const int* __restrict__ ef, int e) {
    int i = blockIdx.x * blockDim.x + threadIdx.x;
    if (i < e) {
        int r = row[i], c = col[i];
        int p = atomicAdd(&g_cur[c], 1);
        g_srow[p]  = r;
        g_skey[p]  = ef[i * 3 + 0] + 5 * ef[i * 3 + 1] + 30 * ef[i * 3 + 2];
        g_snorm[p] = g_dinv[r] * g_dinv[c];
    }
}

// XW GEMM: 32 rows/block, weight fully in smem, 4x4 register microtile
#define TM 32
__global__ void k_gemm(const float* __restrict__ x, const float* __restrict__ w, int n) {
    extern __shared__ float smem[];
    float* wsm = smem;            // 128*128 floats (64 KB), row-major w[k][j]
    float* xs  = smem + C * C;    // 128*32 floats (16 KB), transposed xs[k][r]
    int tid = threadIdx.x;

    // load weight (4096 float4 / 256 threads)
    for (int i = tid; i < C * C / 4; i += 256)
        ((float4*)wsm)[i] = ((const float4*)w)[i];

    int row0 = blockIdx.x * TM;
    // load x tile transposed: xs[k*TM + r] = x[row0+r][k]
    {
        int r   = tid & 31;
        int cg0 = tid >> 5;           // 0..7
        int gr  = row0 + r;
        for (int c4 = cg0; c4 < 32; c4 += 8) {
            float4 v = make_float4(0.f, 0.f, 0.f, 0.f);
            if (gr < n) v = ((const float4*)x)[gr * 32 + c4];
            xs[(4 * c4 + 0) * TM + r] = v.x;
            xs[(4 * c4 + 1) * TM + r] = v.y;
            xs[(4 * c4 + 2) * TM + r] = v.z;
            xs[(4 * c4 + 3) * TM + r] = v.w;
        }
    }
    __syncthreads();

    int tx = tid & 31;   // col group: cols 4*tx..4*tx+3
    int ty = tid >> 5;   // row group: rows 4*ty..4*ty+3
    float acc[4][4] = {};
    #pragma unroll 4
    for (int k = 0; k < C; k++) {
        float4 a = *(const float4*)&xs[k * TM + 4 * ty];
        float4 b = *(const float4*)&wsm[k * C + 4 * tx];
        acc[0][0] += a.x * b.x; acc[0][1] += a.x * b.y; acc[0][2] += a.x * b.z; acc[0][3] += a.x * b.w;
        acc[1][0] += a.y * b.x; acc[1][1] += a.y * b.y; acc[1][2] += a.y * b.z; acc[1][3] += a.y * b.w;
        acc[2][0] += a.z * b.x; acc[2][1] += a.z * b.y; acc[2][2] += a.z * b.z; acc[2][3] += a.z * b.w;
        acc[3][0] += a.w * b.x; acc[3][1] += a.w * b.y; acc[3][2] += a.w * b.z; acc[3][3] += a.w * b.w;
    }
    #pragma unroll
    for (int i = 0; i < 4; i++) {
        int gr = row0 + 4 * ty + i;
        if (gr < n) {
            float4 o = make_float4(acc[i][0], acc[i][1], acc[i][2], acc[i][3]);
            ((float4*)g_xw)[gr * 32 + tx] = o;
        }
    }
}

// aggregation: one warp per destination node, lane owns a float4 of the row.
__global__ void k_agg(float* __restrict__ out, int n) {
    int warp = (blockIdx.x * blockDim.x + threadIdx.x) >> 5;
    int lane = threadIdx.x & 31;
    if (warp >= n) return;
    int beg = g_off[warp], end = g_off[warp + 1];
    float4 acc = make_float4(0.f, 0.f, 0.f, 0.f);
    int j = beg;
    // 2-wide unroll for memory-level parallelism
    for (; j + 1 < end; j += 2) {
        int   r0 = g_srow[j],     r1 = g_srow[j + 1];
        float n0 = g_snorm[j],    n1 = g_snorm[j + 1];
        int   k0 = g_skey[j],     k1 = g_skey[j + 1];
        float4 xv0 = ((const float4*)g_xw)[r0 * 32 + lane];
        float4 xv1 = ((const float4*)g_xw)[r1 * 32 + lane];
        float4 cv0 = ((const float4*)g_combo)[k0 * 32 + lane];
        float4 cv1 = ((const float4*)g_combo)[k1 * 32 + lane];
        acc.x += n0 * (xv0.x + cv0.x) + n1 * (xv1.x + cv1.x);
        acc.y += n0 * (xv0.y + cv0.y) + n1 * (xv1.y + cv1.y);
        acc.z += n0 * (xv0.z + cv0.z) + n1 * (xv1.z + cv1.z);
        acc.w += n0 * (xv0.w + cv0.w) + n1 * (xv1.w + cv1.w);
    }
    if (j < end) {
        int   r0 = g_srow[j];
        float n0 = g_snorm[j];
        int   k0 = g_skey[j];
        float4 xv0 = ((const float4*)g_xw)[r0 * 32 + lane];
        float4 cv0 = ((const float4*)g_combo)[k0 * 32 + lane];
        acc.x += n0 * (xv0.x + cv0.x);
        acc.y += n0 * (xv0.y + cv0.y);
        acc.z += n0 * (xv0.z + cv0.z);
        acc.w += n0 * (xv0.w + cv0.w);
    }
    ((float4*)out)[warp * 32 + lane] = acc;
}

// ---------------- launch ------------------------------------------------------

extern "C" void kernel_launch(void* const* d_in, const int* in_sizes, int n_in,
                              void* d_out, int out_size) {
    const float* x      = (const float*)d_in[0];
    const int*   eidx   = (const int*)d_in[1];
    const int*   efeat  = (const int*)d_in[2];
    const float* weight = (const float*)d_in[3];
    const float* emb0   = (const float*)d_in[4];
    const float* emb1   = (const float*)d_in[5];
    const float* emb2   = (const float*)d_in[6];
    float*       out    = (float*)d_out;

    int n = in_sizes[0] / C;       // 50000
    int e = in_sizes[1] / 2;       // 625000
    const int* row = eidx;
    const int* col = eidx + e;

    // GEMM needs 80 KB dynamic smem
    cudaFuncSetAttribute(k_gemm, cudaFuncAttributeMaxDynamicSharedMemorySize,
                         (C * C + C * TM) * (int)sizeof(float));

    int tpb = 256;
    k_zero   <<<(n + tpb - 1) / tpb, tpb>>>(n);
    k_count  <<<(e + tpb - 1) / tpb, tpb>>>(row, col, e);
    k_dinv   <<<(n + tpb - 1) / tpb, tpb>>>(n);
    k_combo  <<<60, C>>>(emb0, emb1, emb2);
    k_scan   <<<1, 1024>>>(n);
    k_scatter<<<(e + tpb - 1) / tpb, tpb>>>(row, col, efeat, e);
    k_gemm   <<<(n + TM - 1) / TM, 256, (C * C + C * TM) * (int)sizeof(float)>>>(x, weight, n);
    k_agg    <<<(n * 32 + tpb - 1) / tpb, tpb>>>(out, n);
}

// round 2
// speedup vs baseline: 1.9711x; 1.9711x over previous
#include <cuda_runtime.h>
#include <cuda_bf16.h>

#define C 128
#define N_MAX 50000
#define E_MAX 625000

// ---------------- scratch (static device globals; no allocation) -------------
__device__ float g_xw[N_MAX * C];        // X @ W
__device__ float g_dinv[N_MAX];          // deg^{-1/2}
__device__ int   g_deg[N_MAX];           // out-degree by row
__device__ int   g_cnt[N_MAX];           // in-degree by col (CSR counts)
__device__ int   g_off[N_MAX + 1];       // CSR offsets
__device__ int   g_cur[N_MAX];           // scatter cursors
__device__ int   g_bsum[128];            // scan block sums
__device__ int   g_bpre[128];            // scan block prefixes
__device__ int4  g_edge[E_MAX];          // packed by-dest edge: {src, key, norm_bits, 0}
__device__ float g_combo[60 * C];        // emb0[f0]+emb1[f1]+emb2[f2]

// ---------------- small kernels ----------------------------------------------

__global__ void k_zero(int n) {
    int i = blockIdx.x * blockDim.x + threadIdx.x;
    if (i < n) { g_deg[i] = 0; g_cnt[i] = 0; }
}

__global__ void k_count(const int* __restrict__ row, const int* __restrict__ col, int e) {
    int i = blockIdx.x * blockDim.x + threadIdx.x;
    if (i < e) {
        atomicAdd(&g_deg[row[i]], 1);
        atomicAdd(&g_cnt[col[i]], 1);
    }
}

__global__ void k_combo(const float* __restrict__ e0, const float* __restrict__ e1,
                        const float* __restrict__ e2) {
    int c = blockIdx.x;      // 0..59
    int k = threadIdx.x;     // 0..127
    int f0 = c % 5, f1 = (c / 5) % 6, f2 = c / 30;
    g_combo[c * C + k] = e0[f0 * C + k] + e1[f1 * C + k] + e2[f2 * C + k];
}

// -------- 3-stage scan: per-tile exclusive scan, then block sums, then add ---

__global__ void k_scan1(int n) {   // 512 threads / block, 1 elem / thread
    __shared__ int wsum[16];
    int tid = threadIdx.x, lane = tid & 31, wid = tid >> 5;
    int i = blockIdx.x * 512 + tid;
    int v = (i < n) ? g_cnt[i] : 0;
    int x = v;
    #pragma unroll
    for (int o = 1; o < 32; o <<= 1) {
        int t = __shfl_up_sync(0xFFFFFFFFu, x, o);
        if (lane >= o) x += t;
    }
    if (lane == 31) wsum[wid] = x;
    __syncthreads();
    if (wid == 0 && lane < 16) {
        int s = wsum[lane];
        #pragma unroll
        for (int o = 1; o < 16; o <<= 1) {
            int t = __shfl_up_sync(0xFFFFu, s, o);
            if (lane >= o) s += t;
        }
        wsum[lane] = s;
    }
    __syncthreads();
    int incl = x + (wid > 0 ? wsum[wid - 1] : 0);
    if (i < n) g_off[i] = incl - v;          // tile-local exclusive
    if (tid == 511) g_bsum[blockIdx.x] = incl;
}

__global__ void k_scan2(int nb) {  // 1 block, 128 threads: scan block sums
    __shared__ int s[128];
    int tid = threadIdx.x;
    int v = (tid < nb) ? g_bsum[tid] : 0;
    s[tid] = v;
    __syncthreads();
    #pragma unroll
    for (int o = 1; o < 128; o <<= 1) {
        int t = (tid >= o) ? s[tid - o] : 0;
        __syncthreads();
        s[tid] += t;
        __syncthreads();
    }
    g_bpre[tid] = s[tid] - v;                // exclusive
}

__global__ void k_scan3(int n, int e) {      // add prefixes; fused dinv
    int i = blockIdx.x * blockDim.x + threadIdx.x;
    if (i < n) {
        int val = g_off[i] + g_bpre[i >> 9];
        g_off[i] = val;
        g_cur[i] = val;
        int d = g_deg[i];
        g_dinv[i] = (d > 0) ? rsqrtf((float)d) : 0.0f;
    }
    if (i == 0) g_off[n] = e;
}

// bucket edges by destination; packed record per edge
__global__ void k_scatter(const int* __restrict__ row, const int* __restrict__ col,
                          const int* __restrict__ ef, int e) {
    int i = blockIdx.x * blockDim.x + threadIdx.x;
    if (i < e) {
        int r = row[i], c = col[i];
        int p = atomicAdd(&g_cur[c], 1);
        int key = ef[i * 3 + 0] + 5 * ef[i * 3 + 1] + 30 * ef[i * 3 + 2];
        float nrm = g_dinv[r] * g_dinv[c];
        g_edge[p] = make_int4(r, key, __float_as_int(nrm), 0);
    }
}

// ---------------- tf32 tensor-core GEMM --------------------------------------
// Block: 256 thr (8 warps), tile M=64 x N=128, K=128 resident in smem.
// Warp grid 2(m) x 4(n); warp tile 32x32 = 2 m16 x 4 n8 mma tiles.
// A smem [m][k] pitch 132, B smem [n][k] pitch 132 -> all accesses conflict-free.

__device__ __forceinline__ unsigned f2tf(float f) {
    unsigned r;
    asm("cvt.rna.tf32.f32 %0, %1;" : "=r"(r) : "f"(f));
    return r;
}

#define GP 132  // smem pitch (floats)

__global__ void k_gemm(const float* __restrict__ x, const float* __restrict__ w, int n) {
    extern __shared__ unsigned smem[];
    unsigned* As = smem;             // 64  x GP
    unsigned* Bs = smem + 64 * GP;   // 128 x GP   (B stored [n][k])
    int tid = threadIdx.x;
    int row0 = blockIdx.x * 64;

    // fill A: [m][k], coalesced float4 rows
    #pragma unroll
    for (int it = 0; it < 8; it++) {
        int flat = tid + 256 * it;        // 2048 float4s
        int k4 = flat & 31, m = flat >> 5;
        int gr = row0 + m;
        float4 v = make_float4(0.f, 0.f, 0.f, 0.f);
        if (gr < n) v = ((const float4*)x)[gr * 32 + k4];
        unsigned* p = &As[m * GP + 4 * k4];
        p[0] = f2tf(v.x); p[1] = f2tf(v.y); p[2] = f2tf(v.z); p[3] = f2tf(v.w);
    }
    // fill B transposed: read w[k][n] coalesced over n, write Bs[n][k0..k0+3]
    #pragma unroll
    for (int it = 0; it < 16; it++) {
        int flat = tid + 256 * it;        // 4096 quads
        int nn = flat & 127, k0 = 4 * (flat >> 7);
        unsigned q0 = f2tf(w[(k0 + 0) * C + nn]);
        unsigned q1 = f2tf(w[(k0 + 1) * C + nn]);
        unsigned q2 = f2tf(w[(k0 + 2) * C + nn]);
        unsigned q3 = f2tf(w[(k0 + 3) * C + nn]);
        unsigned* p = &Bs[nn * GP + k0];
        p[0] = q0; p[1] = q1; p[2] = q2; p[3] = q3;
    }
    __syncthreads();

    int wid = tid >> 5, lane = tid & 31;
    int g = lane >> 2, t4 = lane & 3;
    int wm = (wid & 1) * 32;     // warp m base
    int wn = (wid >> 1) * 32;    // warp n base

    float c[2][4][4];
    #pragma unroll
    for (int a = 0; a < 2; a++)
        #pragma unroll
        for (int b = 0; b < 4; b++)
            #pragma unroll
            for (int k = 0; k < 4; k++) c[a][b][k] = 0.f;

    #pragma unroll
    for (int s = 0; s < 16; s++) {
        int k0 = s * 8;
        unsigned a0[2], a1[2], a2[2], a3[2];
        #pragma unroll
        for (int mt = 0; mt < 2; mt++) {
            const unsigned* ap = &As[(wm + mt * 16 + g) * GP + k0 + t4];
            a0[mt] = ap[0];
            a1[mt] = ap[8 * GP];
            a2[mt] = ap[4];
            a3[mt] = ap[8 * GP + 4];
        }
        unsigned b0[4], b1[4];
        #pragma unroll
        for (int nt = 0; nt < 4; nt++) {
            const unsigned* bp = &Bs[(wn + nt * 8 + g) * GP + k0 + t4];
            b0[nt] = bp[0];
            b1[nt] = bp[4];
        }
        #pragma unroll
        for (int mt = 0; mt < 2; mt++)
            #pragma unroll
            for (int nt = 0; nt < 4; nt++) {
                asm volatile(
                    "mma.sync.aligned.m16n8k8.row.col.f32.tf32.tf32.f32 "
                    "{%0,%1,%2,%3},{%4,%5,%6,%7},{%8,%9},{%0,%1,%2,%3};\n"
                    : "+f"(c[mt][nt][0]), "+f"(c[mt][nt][1]),
                      "+f"(c[mt][nt][2]), "+f"(c[mt][nt][3])
                    : "r"(a0[mt]), "r"(a1[mt]), "r"(a2[mt]), "r"(a3[mt]),
                      "r"(b0[nt]), "r"(b1[nt]));
            }
    }

    // store: c0/c1 -> (row, col..col+1), c2/c3 -> (row+8, ...)
    #pragma unroll
    for (int mt = 0; mt < 2; mt++) {
        int r_lo = row0 + wm + mt * 16 + g;
        int r_hi = r_lo + 8;
        #pragma unroll
        for (int nt = 0; nt < 4; nt++) {
            int colw = (wn + nt * 8 + 2 * t4) >> 1;  // float2 index
            if (r_lo < n)
                ((float2*)g_xw)[r_lo * 64 + colw] = make_float2(c[mt][nt][0], c[mt][nt][1]);
            if (r_hi < n)
                ((float2*)g_xw)[r_hi * 64 + colw] = make_float2(c[mt][nt][2], c[mt][nt][3]);
        }
    }
}

// ---------------- aggregation: one warp per destination node ------------------
__global__ void k_agg(float* __restrict__ out, int n) {
    int warp = (blockIdx.x * blockDim.x + threadIdx.x) >> 5;
    int lane = threadIdx.x & 31;
    if (warp >= n) return;
    int beg = g_off[warp], end = g_off[warp + 1];
    float4 acc = make_float4(0.f, 0.f, 0.f, 0.f);
    int j = beg;
    for (; j + 1 < end; j += 2) {
        int4 m0 = g_edge[j];
        int4 m1 = g_edge[j + 1];
        float n0 = __int_as_float(m0.z), n1 = __int_as_float(m1.z);
        float4 xv0 = ((const float4*)g_xw)[m0.x * 32 + lane];
        float4 xv1 = ((const float4*)g_xw)[m1.x * 32 + lane];
        float4 cv0 = ((const float4*)g_combo)[m0.y * 32 + lane];
        float4 cv1 = ((const float4*)g_combo)[m1.y * 32 + lane];
        acc.x += n0 * (xv0.x + cv0.x) + n1 * (xv1.x + cv1.x);
        acc.y += n0 * (xv0.y + cv0.y) + n1 * (xv1.y + cv1.y);
        acc.z += n0 * (xv0.z + cv0.z) + n1 * (xv1.z + cv1.z);
        acc.w += n0 * (xv0.w + cv0.w) + n1 * (xv1.w + cv1.w);
    }
    if (j < end) {
        int4 m0 = g_edge[j];
        float n0 = __int_as_float(m0.z);
        float4 xv0 = ((const float4*)g_xw)[m0.x * 32 + lane];
        float4 cv0 = ((const float4*)g_combo)[m0.y * 32 + lane];
        acc.x += n0 * (xv0.x + cv0.x);
        acc.y += n0 * (xv0.y + cv0.y);
        acc.z += n0 * (xv0.z + cv0.z);
        acc.w += n0 * (xv0.w + cv0.w);
    }
    ((float4*)out)[warp * 32 + lane] = acc;
}

// ---------------- launch ------------------------------------------------------

extern "C" void kernel_launch(void* const* d_in, const int* in_sizes, int n_in,
                              void* d_out, int out_size) {
    const float* x      = (const float*)d_in[0];
    const int*   eidx   = (const int*)d_in[1];
    const int*   efeat  = (const int*)d_in[2];
    const float* weight = (const float*)d_in[3];
    const float* emb0   = (const float*)d_in[4];
    const float* emb1   = (const float*)d_in[5];
    const float* emb2   = (const float*)d_in[6];
    float*       out    = (float*)d_out;

    int n = in_sizes[0] / C;       // 50000
    int e = in_sizes[1] / 2;       // 625000
    const int* row = eidx;
    const int* col = eidx + e;

    int gemm_smem = (64 + 128) * GP * (int)sizeof(unsigned);  // 101376
    cudaFuncSetAttribute(k_gemm, cudaFuncAttributeMaxDynamicSharedMemorySize, gemm_smem);

    int tpb = 256;
    int nb = (n + 511) / 512;      // scan tiles (98 <= 128)
    k_zero   <<<(n + tpb - 1) / tpb, tpb>>>(n);
    k_count  <<<(e + tpb - 1) / tpb, tpb>>>(row, col, e);
    k_combo  <<<60, C>>>(emb0, emb1, emb2);
    k_scan1  <<<nb, 512>>>(n);
    k_scan2  <<<1, 128>>>(nb);
    k_scan3  <<<(n + tpb - 1) / tpb, tpb>>>(n, e);
    k_scatter<<<(e + tpb - 1) / tpb, tpb>>>(row, col, efeat, e);
    k_gemm   <<<(n + 63) / 64, 256, gemm_smem>>>(x, weight, n);
    k_agg    <<<(n * 32 + tpb - 1) / tpb, tpb>>>(out, n);
}

// round 3
// speedup vs baseline: 2.1807x; 1.1064x over previous
#include <cuda_runtime.h>
#include <cuda_fp16.h>
#include <cuda_bf16.h>

#define C 128
#define N_MAX 50000
#define E_MAX 625000

// ---------------- scratch (static device globals; no allocation) -------------
__device__ __half g_xwh[N_MAX * C];      // X @ W, fp16
__device__ float g_dinv[N_MAX];          // deg^{-1/2}
__device__ int   g_deg[N_MAX];           // out-degree by row
__device__ int   g_cnt[N_MAX];           // in-degree by col (CSR counts)
__device__ int   g_off[N_MAX + 1];       // CSR offsets
__device__ int   g_cur[N_MAX];           // scatter cursors
__device__ int   g_bsum[128];            // scan block sums
__device__ int2  g_edge[E_MAX];          // packed: {src | key<<16, norm_bits}
__device__ float g_combo[60 * C];        // emb0[f0]+emb1[f1]+emb2[f2]

// ---------------- fused init: zero counters + combo table --------------------
__global__ void k_init(int n, const float* __restrict__ e0,
                       const float* __restrict__ e1, const float* __restrict__ e2) {
    int i = blockIdx.x * blockDim.x + threadIdx.x;
    if (i < n) { g_deg[i] = 0; g_cnt[i] = 0; }
    if (i < 60 * C) {
        int c = i >> 7, k = i & 127;
        int f0 = c % 5, f1 = (c / 5) % 6, f2 = c / 30;
        g_combo[i] = e0[f0 * C + k] + e1[f1 * C + k] + e2[f2 * C + k];
    }
}

__global__ void k_count(const int* __restrict__ row, const int* __restrict__ col, int e) {
    int i = blockIdx.x * blockDim.x + threadIdx.x;
    if (i < e) {
        atomicAdd(&g_deg[row[i]], 1);
        atomicAdd(&g_cnt[col[i]], 1);
    }
}

// -------- scan stage 1: tile-local exclusive scan + block sums + fused dinv --
__global__ void k_scan1(int n) {   // 512 threads / block, 1 elem / thread
    __shared__ int wsum[16];
    int tid = threadIdx.x, lane = tid & 31, wid = tid >> 5;
    int i = blockIdx.x * 512 + tid;
    int v = (i < n) ? g_cnt[i] : 0;
    int x = v;
    #pragma unroll
    for (int o = 1; o < 32; o <<= 1) {
        int t = __shfl_up_sync(0xFFFFFFFFu, x, o);
        if (lane >= o) x += t;
    }
    if (lane == 31) wsum[wid] = x;
    __syncthreads();
    if (wid == 0 && lane < 16) {
        int s = wsum[lane];
        #pragma unroll
        for (int o = 1; o < 16; o <<= 1) {
            int t = __shfl_up_sync(0xFFFFu, s, o);
            if (lane >= o) s += t;
        }
        wsum[lane] = s;
    }
    __syncthreads();
    int incl = x + (wid > 0 ? wsum[wid - 1] : 0);
    if (i < n) {
        g_off[i] = incl - v;          // tile-local exclusive
        int d = g_deg[i];
        g_dinv[i] = (d > 0) ? rsqrtf((float)d) : 0.0f;
    }
    if (tid == 511) g_bsum[blockIdx.x] = incl;
}

// -------- scan stage 2+3 fused: every block redundantly scans block sums -----
__global__ void k_scan23(int n, int nb, int e) {
    __shared__ int s[128];
    int tid = threadIdx.x;
    if (tid < 128) s[tid] = (tid < nb) ? g_bsum[tid] : 0;
    __syncthreads();
    #pragma unroll
    for (int o = 1; o < 128; o <<= 1) {
        int t = (tid < 128 && tid >= o) ? s[tid - o] : 0;
        __syncthreads();
        if (tid < 128) s[tid] += t;
        __syncthreads();
    }
    int off = (blockIdx.x > 0) ? s[blockIdx.x - 1] : 0;
    int i = blockIdx.x * 512 + tid;
    if (i < n) {
        int val = g_off[i] + off;
        g_off[i] = val;
        g_cur[i] = val;
    }
    if (i == 0) g_off[n] = e;
}

// bucket edges by destination; packed 8-byte record per edge
__global__ void k_scatter(const int* __restrict__ row, const int* __restrict__ col,
                          const int* __restrict__ ef, int e) {
    int i = blockIdx.x * blockDim.x + threadIdx.x;
    if (i < e) {
        int r = row[i], c = col[i];
        int p = atomicAdd(&g_cur[c], 1);
        int key = ef[i * 3 + 0] + 5 * ef[i * 3 + 1] + 30 * ef[i * 3 + 2];
        float nrm = g_dinv[r] * g_dinv[c];
        g_edge[p] = make_int2(r | (key << 16), __float_as_int(nrm));
    }
}

// ---------------- tf32 tensor-core GEMM (fp16 output) ------------------------
__device__ __forceinline__ unsigned f2tf(float f) {
    unsigned r;
    asm("cvt.rna.tf32.f32 %0, %1;" : "=r"(r) : "f"(f));
    return r;
}

#define GP 132  // smem pitch (floats)

__global__ void k_gemm(const float* __restrict__ x, const float* __restrict__ w, int n) {
    extern __shared__ unsigned smem[];
    unsigned* As = smem;             // 64  x GP
    unsigned* Bs = smem + 64 * GP;   // 128 x GP   (B stored [n][k])
    int tid = threadIdx.x;
    int row0 = blockIdx.x * 64;

    #pragma unroll
    for (int it = 0; it < 8; it++) {
        int flat = tid + 256 * it;        // 2048 float4s
        int k4 = flat & 31, m = flat >> 5;
        int gr = row0 + m;
        float4 v = make_float4(0.f, 0.f, 0.f, 0.f);
        if (gr < n) v = ((const float4*)x)[gr * 32 + k4];
        unsigned* p = &As[m * GP + 4 * k4];
        p[0] = f2tf(v.x); p[1] = f2tf(v.y); p[2] = f2tf(v.z); p[3] = f2tf(v.w);
    }
    #pragma unroll
    for (int it = 0; it < 16; it++) {
        int flat = tid + 256 * it;        // 4096 quads
        int nn = flat & 127, k0 = 4 * (flat >> 7);
        unsigned q0 = f2tf(w[(k0 + 0) * C + nn]);
        unsigned q1 = f2tf(w[(k0 + 1) * C + nn]);
        unsigned q2 = f2tf(w[(k0 + 2) * C + nn]);
        unsigned q3 = f2tf(w[(k0 + 3) * C + nn]);
        unsigned* p = &Bs[nn * GP + k0];
        p[0] = q0; p[1] = q1; p[2] = q2; p[3] = q3;
    }
    __syncthreads();

    int wid = tid >> 5, lane = tid & 31;
    int g = lane >> 2, t4 = lane & 3;
    int wm = (wid & 1) * 32;     // warp m base
    int wn = (wid >> 1) * 32;    // warp n base

    float c[2][4][4];
    #pragma unroll
    for (int a = 0; a < 2; a++)
        #pragma unroll
        for (int b = 0; b < 4; b++)
            #pragma unroll
            for (int k = 0; k < 4; k++) c[a][b][k] = 0.f;

    #pragma unroll
    for (int s = 0; s < 16; s++) {
        int k0 = s * 8;
        unsigned a0[2], a1[2], a2[2], a3[2];
        #pragma unroll
        for (int mt = 0; mt < 2; mt++) {
            const unsigned* ap = &As[(wm + mt * 16 + g) * GP + k0 + t4];
            a0[mt] = ap[0];
            a1[mt] = ap[8 * GP];
            a2[mt] = ap[4];
            a3[mt] = ap[8 * GP + 4];
        }
        unsigned b0[4], b1[4];
        #pragma unroll
        for (int nt = 0; nt < 4; nt++) {
            const unsigned* bp = &Bs[(wn + nt * 8 + g) * GP + k0 + t4];
            b0[nt] = bp[0];
            b1[nt] = bp[4];
        }
        #pragma unroll
        for (int mt = 0; mt < 2; mt++)
            #pragma unroll
            for (int nt = 0; nt < 4; nt++) {
                asm volatile(
                    "mma.sync.aligned.m16n8k8.row.col.f32.tf32.tf32.f32 "
                    "{%0,%1,%2,%3},{%4,%5,%6,%7},{%8,%9},{%0,%1,%2,%3};\n"
                    : "+f"(c[mt][nt][0]), "+f"(c[mt][nt][1]),
                      "+f"(c[mt][nt][2]), "+f"(c[mt][nt][3])
                    : "r"(a0[mt]), "r"(a1[mt]), "r"(a2[mt]), "r"(a3[mt]),
                      "r"(b0[nt]), "r"(b1[nt]));
            }
    }

    #pragma unroll
    for (int mt = 0; mt < 2; mt++) {
        int r_lo = row0 + wm + mt * 16 + g;
        int r_hi = r_lo + 8;
        #pragma unroll
        for (int nt = 0; nt < 4; nt++) {
            int colp = wn + nt * 8 + 2 * t4;
            if (r_lo < n)
                *(__half2*)&g_xwh[r_lo * C + colp] = __floats2half2_rn(c[mt][nt][0], c[mt][nt][1]);
            if (r_hi < n)
                *(__half2*)&g_xwh[r_hi * C + colp] = __floats2half2_rn(c[mt][nt][2], c[mt][nt][3]);
        }
    }
}

// ---------------- aggregation: one warp per destination node ------------------
__device__ __forceinline__ void agg_edge(int2 m, int lane, float4& acc) {
    int src = m.x & 0xFFFF;
    int key = m.x >> 16;
    float nrm = __int_as_float(m.y);
    uint2 h = ((const uint2*)g_xwh)[src * 32 + lane];        // 4 fp16 channels
    float2 lo = __half22float2(*(__half2*)&h.x);
    float2 hi = __half22float2(*(__half2*)&h.y);
    float4 cv = ((const float4*)g_combo)[key * 32 + lane];
    acc.x += nrm * (lo.x + cv.x);
    acc.y += nrm * (lo.y + cv.y);
    acc.z += nrm * (hi.x + cv.z);
    acc.w += nrm * (hi.y + cv.w);
}

__global__ void k_agg(float* __restrict__ out, int n) {
    int warp = (blockIdx.x * blockDim.x + threadIdx.x) >> 5;
    int lane = threadIdx.x & 31;
    if (warp >= n) return;
    int beg = g_off[warp], end = g_off[warp + 1];
    float4 acc = make_float4(0.f, 0.f, 0.f, 0.f);
    int j = beg;
    for (; j + 3 < end; j += 4) {
        int2 m0 = g_edge[j];
        int2 m1 = g_edge[j + 1];
        int2 m2 = g_edge[j + 2];
        int2 m3 = g_edge[j + 3];
        agg_edge(m0, lane, acc);
        agg_edge(m1, lane, acc);
        agg_edge(m2, lane, acc);
        agg_edge(m3, lane, acc);
    }
    for (; j < end; j++) {
        agg_edge(g_edge[j], lane, acc);
    }
    ((float4*)out)[warp * 32 + lane] = acc;
}

// ---------------- launch ------------------------------------------------------

extern "C" void kernel_launch(void* const* d_in, const int* in_sizes, int n_in,
                              void* d_out, int out_size) {
    const float* x      = (const float*)d_in[0];
    const int*   eidx   = (const int*)d_in[1];
    const int*   efeat  = (const int*)d_in[2];
    const float* weight = (const float*)d_in[3];
    const float* emb0   = (const float*)d_in[4];
    const float* emb1   = (const float*)d_in[5];
    const float* emb2   = (const float*)d_in[6];
    float*       out    = (float*)d_out;

    int n = in_sizes[0] / C;       // 50000
    int e = in_sizes[1] / 2;       // 625000
    const int* row = eidx;
    const int* col = eidx + e;

    int gemm_smem = (64 + 128) * GP * (int)sizeof(unsigned);  // 101376
    cudaFuncSetAttribute(k_gemm, cudaFuncAttributeMaxDynamicSharedMemorySize, gemm_smem);

    int tpb = 256;
    int nb = (n + 511) / 512;      // scan tiles (98 <= 128)
    k_init   <<<(n + tpb - 1) / tpb, tpb>>>(n, emb0, emb1, emb2);
    k_count  <<<(e + tpb - 1) / tpb, tpb>>>(row, col, e);
    k_scan1  <<<nb, 512>>>(n);
    k_scan23 <<<nb, 512>>>(n, nb, e);
    k_scatter<<<(e + tpb - 1) / tpb, tpb>>>(row, col, efeat, e);
    k_gemm   <<<(n + 63) / 64, 256, gemm_smem>>>(x, weight, n);
    k_agg    <<<(n * 32 + tpb - 1) / tpb, tpb>>>(out, n);
}